// round 1
// baseline (speedup 1.0000x reference)
#include <cuda_runtime.h>
#include <cuda_bf16.h>

#define B 4
#define L 512
#define D 128
#define QT 4            // queries per block in attn kernel
#define KT 64           // keys per smem slab
#define EPSV 1e-8f

// scratch (device globals: allocation-free)
__device__ float g_qb[B * L * D];   // q + bh, row-major [b*L + l][d]
__device__ float g_k [B * L * D];   // k, row-major
__device__ float g_kT[B * L * D];   // k transposed per batch: [b][d][l]

__device__ __forceinline__ float tanh_fast(float x) {
    float y;
    asm("tanh.approx.f32 %0, %1;" : "=f"(y) : "f"(x));
    return y;
}

// accurate tanh: 1 - 2/(e^{2x}+1); handles +/-inf overflow gracefully
__device__ __forceinline__ float tanh_acc(float x) {
    float e2 = __expf(2.0f * x);
    return 1.0f - __fdividef(2.0f, e2 + 1.0f);
}

// ---------------------------------------------------------------------------
// Kernel A: qb = X @ Wt + bh ; k = X @ Wx  (+ transposed copy of k)
// grid: (B*L)/16 = 128 blocks, 128 threads (one per output column)
// ---------------------------------------------------------------------------
__global__ __launch_bounds__(128) void qk_kernel(
    const float* __restrict__ X, const float* __restrict__ Wt,
    const float* __restrict__ Wx, const float* __restrict__ bh)
{
    __shared__ float Xs[16][D];
    const int row0 = blockIdx.x * 16;
    const int tid = threadIdx.x;

    // load 16 input rows (coalesced float4)
    {
        const float4* Xg = (const float4*)(X + row0 * D);
        float4* Xs4 = (float4*)(&Xs[0][0]);
        #pragma unroll
        for (int i = tid; i < 16 * (D / 4); i += 128) Xs4[i] = Xg[i];
    }
    __syncthreads();

    const int c = tid;
    float accq[16], acck[16];
    #pragma unroll
    for (int r = 0; r < 16; r++) { accq[r] = 0.f; acck[r] = 0.f; }

    for (int d4 = 0; d4 < D / 4; d4++) {
        float wt0 = Wt[(d4 * 4 + 0) * D + c], wx0 = Wx[(d4 * 4 + 0) * D + c];
        float wt1 = Wt[(d4 * 4 + 1) * D + c], wx1 = Wx[(d4 * 4 + 1) * D + c];
        float wt2 = Wt[(d4 * 4 + 2) * D + c], wx2 = Wx[(d4 * 4 + 2) * D + c];
        float wt3 = Wt[(d4 * 4 + 3) * D + c], wx3 = Wx[(d4 * 4 + 3) * D + c];
        #pragma unroll
        for (int r = 0; r < 16; r++) {
            float4 xv = *(const float4*)&Xs[r][d4 * 4];
            accq[r] = fmaf(xv.x, wt0, accq[r]); acck[r] = fmaf(xv.x, wx0, acck[r]);
            accq[r] = fmaf(xv.y, wt1, accq[r]); acck[r] = fmaf(xv.y, wx1, acck[r]);
            accq[r] = fmaf(xv.z, wt2, accq[r]); acck[r] = fmaf(xv.z, wx2, acck[r]);
            accq[r] = fmaf(xv.w, wt3, accq[r]); acck[r] = fmaf(xv.w, wx3, acck[r]);
        }
    }

    const float bhc = bh[c];
    #pragma unroll
    for (int r = 0; r < 16; r++) {
        int row = row0 + r;
        g_qb[row * D + c] = accq[r] + bhc;
        g_k [row * D + c] = acck[r];
        int b = row >> 9, l = row & (L - 1);
        g_kT[b * (D * L) + c * L + l] = acck[r];   // scattered, tiny volume
    }
}

// ---------------------------------------------------------------------------
// Kernel B: row max over all keys (approx tanh) + window softmax + output
// grid: (L/QT, B) = (128, 4); 128 threads; warp == query
// ---------------------------------------------------------------------------
__global__ __launch_bounds__(128) void attn_kernel(
    const float* __restrict__ X, const float* __restrict__ Wa,
    const float* __restrict__ ba_p, float* __restrict__ out)
{
    __shared__ float ksT[D][KT + 4];   // [d][key], pad 4 -> conflict-free lane=key reads
    __shared__ float qs[QT][D + 4];

    const int b   = blockIdx.y;
    const int q0  = blockIdx.x * QT;
    const int tid = threadIdx.x;
    const int q   = tid >> 5;
    const int lane = tid & 31;

    const float* qbB = g_qb + (b * L + q0) * D;
    const float* kTB = g_kT + b * (D * L);

    // load query tile (qb already includes bh)
    for (int i = tid; i < QT * (D / 4); i += 128) {
        int r = i >> 5, d4 = i & 31;
        *(float4*)&qs[r][d4 * 4] = ((const float4*)(qbB + r * D))[d4];
    }

    float m = -1e30f;

    for (int t = 0; t < L / KT; t++) {
        __syncthreads();
        // load 64-key slab of kT: ksT[d][0..63]
        for (int i = tid; i < D * (KT / 4); i += 128) {
            int d = i >> 4, r4 = i & 15;
            *(float4*)&ksT[d][r4 * 4] = ((const float4*)(kTB + d * L + t * KT))[r4];
        }
        __syncthreads();

        float acc0 = 0.f, acc1 = 0.f;        // keys: lane, lane+32
        #pragma unroll
        for (int c = 0; c < 4; c++) {        // 4 chunks of 32 dims
            float4 qv[8], wv[8];
            #pragma unroll
            for (int u = 0; u < 8; u++) {
                qv[u] = *(const float4*)&qs[q][c * 32 + u * 4];
                wv[u] = ((const float4*)Wa)[c * 8 + u];
            }
            #pragma unroll
            for (int u = 0; u < 8; u++) {
                int dd = c * 32 + u * 4;
                acc0 += tanh_fast(qv[u].x + ksT[dd + 0][lane     ]) * wv[u].x;
                acc1 += tanh_fast(qv[u].x + ksT[dd + 0][lane + 32]) * wv[u].x;
                acc0 += tanh_fast(qv[u].y + ksT[dd + 1][lane     ]) * wv[u].y;
                acc1 += tanh_fast(qv[u].y + ksT[dd + 1][lane + 32]) * wv[u].y;
                acc0 += tanh_fast(qv[u].z + ksT[dd + 2][lane     ]) * wv[u].z;
                acc1 += tanh_fast(qv[u].z + ksT[dd + 2][lane + 32]) * wv[u].z;
                acc0 += tanh_fast(qv[u].w + ksT[dd + 3][lane     ]) * wv[u].w;
                acc1 += tanh_fast(qv[u].w + ksT[dd + 3][lane + 32]) * wv[u].w;
            }
        }
        m = fmaxf(m, fmaxf(acc0, acc1));
    }

    // warp all-reduce max -> row max for query q0+q (ba cancels; omit)
    #pragma unroll
    for (int o = 16; o > 0; o >>= 1)
        m = fmaxf(m, __shfl_xor_sync(0xffffffffu, m, o));

    // ------- window phase (accurate tanh), warp == query -------
    const int qi = q0 + q;
    const float* kB = g_k + (b * L) * D;
    const float* XB = X + (b * L) * D;
    const float bav = ba_p[0];

    float4 qv4 = *(const float4*)&qs[q][lane * 4];
    float4 wv4 = ((const float4*)Wa)[lane];

    float w[3];
    float s = EPSV;
    #pragma unroll
    for (int tt = 0; tt < 3; tt++) {
        int j = qi - 1 + tt;
        if (j >= 0 && j < L) {
            float4 kv = ((const float4*)(kB + j * D))[lane];
            float p = tanh_acc(qv4.x + kv.x) * wv4.x
                    + tanh_acc(qv4.y + kv.y) * wv4.y
                    + tanh_acc(qv4.z + kv.z) * wv4.z
                    + tanh_acc(qv4.w + kv.w) * wv4.w;
            #pragma unroll
            for (int o = 16; o > 0; o >>= 1)
                p += __shfl_xor_sync(0xffffffffu, p, o);
            w[tt] = __expf(p + bav - m);
        } else {
            w[tt] = 0.f;
        }
        s += w[tt];
    }
    float inv = __fdividef(1.0f, s);

    float4 o4 = make_float4(0.f, 0.f, 0.f, 0.f);
    #pragma unroll
    for (int tt = 0; tt < 3; tt++) {
        int j = qi - 1 + tt;
        if (j >= 0 && j < L && w[tt] != 0.f) {
            float a = w[tt] * inv;
            float4 xv = ((const float4*)(XB + j * D))[lane];
            o4.x += a * xv.x; o4.y += a * xv.y;
            o4.z += a * xv.z; o4.w += a * xv.w;
        }
    }
    ((float4*)(out + (b * L + qi) * D))[lane] = o4;
}

extern "C" void kernel_launch(void* const* d_in, const int* in_sizes, int n_in,
                              void* d_out, int out_size)
{
    const float* X  = (const float*)d_in[0];
    const float* Wt = (const float*)d_in[1];
    const float* Wx = (const float*)d_in[2];
    const float* Wa = (const float*)d_in[3];
    const float* bh = (const float*)d_in[4];
    const float* ba = (const float*)d_in[5];
    float* out = (float*)d_out;

    qk_kernel<<<(B * L) / 16, 128>>>(X, Wt, Wx, bh);
    dim3 grid(L / QT, B);
    attn_kernel<<<grid, 128>>>(X, Wa, ba, out);
}

// round 2
// speedup vs baseline: 4.3692x; 4.3692x over previous
#include <cuda_runtime.h>
#include <cuda_bf16.h>

#define B 4
#define L 512
#define D 128
#define ROWS 8          // rows per block in GEMM kernel
#define QW 8            // queries (warps) per block in window kernel
#define EPSV 1e-8f

// scratch (device globals: allocation-free)
__device__ float g_qb[B * L * D];   // X@Wt + bh, row-major
__device__ float g_k [B * L * D];   // X@Wx,      row-major

// accurate tanh: 1 - 2/(e^{2x}+1)
__device__ __forceinline__ float tanh_acc(float x) {
    float e2 = __expf(2.0f * x);
    return 1.0f - __fdividef(2.0f, e2 + 1.0f);
}

// ---------------------------------------------------------------------------
// Kernel A: qb = X @ Wt + bh ; k = X @ Wx
// grid: (B*L)/ROWS = 256 blocks, 128 threads (one per output column)
// ---------------------------------------------------------------------------
__global__ __launch_bounds__(128) void qk_kernel(
    const float* __restrict__ X, const float* __restrict__ Wt,
    const float* __restrict__ Wx, const float* __restrict__ bh)
{
    __shared__ float Xs[ROWS][D];
    const int row0 = blockIdx.x * ROWS;
    const int tid = threadIdx.x;

    // load ROWS input rows (coalesced float4)
    {
        const float4* Xg = (const float4*)(X + row0 * D);
        float4* Xs4 = (float4*)(&Xs[0][0]);
        #pragma unroll
        for (int i = tid; i < ROWS * (D / 4); i += 128) Xs4[i] = Xg[i];
    }
    __syncthreads();

    const int c = tid;
    float accq[ROWS], acck[ROWS];
    #pragma unroll
    for (int r = 0; r < ROWS; r++) { accq[r] = 0.f; acck[r] = 0.f; }

    #pragma unroll 2
    for (int d4 = 0; d4 < D / 4; d4++) {
        float wt0 = Wt[(d4 * 4 + 0) * D + c], wx0 = Wx[(d4 * 4 + 0) * D + c];
        float wt1 = Wt[(d4 * 4 + 1) * D + c], wx1 = Wx[(d4 * 4 + 1) * D + c];
        float wt2 = Wt[(d4 * 4 + 2) * D + c], wx2 = Wx[(d4 * 4 + 2) * D + c];
        float wt3 = Wt[(d4 * 4 + 3) * D + c], wx3 = Wx[(d4 * 4 + 3) * D + c];
        #pragma unroll
        for (int r = 0; r < ROWS; r++) {
            float4 xv = *(const float4*)&Xs[r][d4 * 4];
            accq[r] = fmaf(xv.x, wt0, accq[r]); acck[r] = fmaf(xv.x, wx0, acck[r]);
            accq[r] = fmaf(xv.y, wt1, accq[r]); acck[r] = fmaf(xv.y, wx1, acck[r]);
            accq[r] = fmaf(xv.z, wt2, accq[r]); acck[r] = fmaf(xv.z, wx2, acck[r]);
            accq[r] = fmaf(xv.w, wt3, accq[r]); acck[r] = fmaf(xv.w, wx3, acck[r]);
        }
    }

    const float bhc = bh[c];
    #pragma unroll
    for (int r = 0; r < ROWS; r++) {
        int row = row0 + r;
        g_qb[row * D + c] = accq[r] + bhc;
        g_k [row * D + c] = acck[r];
    }
}

// ---------------------------------------------------------------------------
// Kernel B: window-only softmax + output. warp == query.
// a_j = exp(e_j - m_win) / (sum_win exp(e - m_win) + EPS)
// (difference vs full-row max is a common factor 1 + O(EPS * e^{M - m_win}))
// grid: (L/QW, B), 256 threads
// ---------------------------------------------------------------------------
__global__ __launch_bounds__(256) void window_kernel(
    const float* __restrict__ X, const float* __restrict__ Wa,
    const float* __restrict__ ba_p, float* __restrict__ out)
{
    const int b    = blockIdx.y;
    const int qi   = blockIdx.x * QW + (threadIdx.x >> 5);
    const int lane = threadIdx.x & 31;

    const float* kB = g_k + (b * L) * D;
    const float* XB = X + (b * L) * D;

    float4 qv = ((const float4*)(g_qb + (b * L + qi) * D))[lane];
    float4 wv = ((const float4*)Wa)[lane];
    const float bav = ba_p[0];

    float e[3];
    #pragma unroll
    for (int tt = 0; tt < 3; tt++) {
        int j = qi - 1 + tt;
        int jc = min(max(j, 0), L - 1);          // clamped for safe load
        float4 kv = ((const float4*)(kB + jc * D))[lane];
        float p = tanh_acc(qv.x + kv.x) * wv.x
                + tanh_acc(qv.y + kv.y) * wv.y
                + tanh_acc(qv.z + kv.z) * wv.z
                + tanh_acc(qv.w + kv.w) * wv.w;
        #pragma unroll
        for (int o = 16; o > 0; o >>= 1)
            p += __shfl_xor_sync(0xffffffffu, p, o);
        e[tt] = (j >= 0 && j < L) ? (p + bav) : -1e30f;
    }

    float m = fmaxf(e[0], fmaxf(e[1], e[2]));
    float w0 = __expf(e[0] - m);
    float w1 = __expf(e[1] - m);
    float w2 = __expf(e[2] - m);
    float inv = __fdividef(1.0f, w0 + w1 + w2 + EPSV);

    float4 o4 = make_float4(0.f, 0.f, 0.f, 0.f);
    #pragma unroll
    for (int tt = 0; tt < 3; tt++) {
        int j = qi - 1 + tt;
        int jc = min(max(j, 0), L - 1);
        float w = (tt == 0) ? w0 : (tt == 1) ? w1 : w2;
        float a = w * inv;
        if (j >= 0 && j < L && a != 0.f) {
            float4 xv = ((const float4*)(XB + jc * D))[lane];
            o4.x += a * xv.x; o4.y += a * xv.y;
            o4.z += a * xv.z; o4.w += a * xv.w;
        }
    }
    ((float4*)(out + (b * L + qi) * D))[lane] = o4;
}

extern "C" void kernel_launch(void* const* d_in, const int* in_sizes, int n_in,
                              void* d_out, int out_size)
{
    const float* X  = (const float*)d_in[0];
    const float* Wt = (const float*)d_in[1];
    const float* Wx = (const float*)d_in[2];
    const float* Wa = (const float*)d_in[3];
    const float* bh = (const float*)d_in[4];
    const float* ba = (const float*)d_in[5];
    float* out = (float*)d_out;

    qk_kernel<<<(B * L) / ROWS, 128>>>(X, Wt, Wx, bh);
    dim3 grid(L / QW, B);
    window_kernel<<<grid, 256>>>(X, Wa, ba, out);
}